// round 10
// baseline (speedup 1.0000x reference)
#include <cuda_runtime.h>
#include <cuda_bf16.h>
#include <math.h>
#include <cstdint>

#define BATCH   64
#define DIMC    64
#define HEADS   8
#define DHEAD   64
#define INNER   512
#define MLPD    256
#define DEPTH   4
#define NPATCH  225
#define NTOK    226
#define M2      (2*BATCH*NTOK)   /* 28928 rows */
#define MBTOT   (M2/16)          /* 1808 m-blocks */
#define EPSV    1e-5f
#define SCALEV  0.125f

/* ---------------- mma helpers ---------------- */
__device__ __forceinline__ uint32_t smem_u32(const void* p) {
    uint32_t a;
    asm("{ .reg .u64 t; cvta.to.shared.u64 t, %1; cvt.u32.u64 %0, t; }" : "=r"(a) : "l"(p));
    return a;
}
__device__ __forceinline__ void mma_bf16(float* c, const uint32_t* a, const uint32_t* b) {
    asm volatile("mma.sync.aligned.m16n8k16.row.col.f32.bf16.bf16.f32 "
        "{%0,%1,%2,%3}, {%4,%5,%6,%7}, {%8,%9}, {%0,%1,%2,%3};"
        : "+f"(c[0]), "+f"(c[1]), "+f"(c[2]), "+f"(c[3])
        : "r"(a[0]), "r"(a[1]), "r"(a[2]), "r"(a[3]), "r"(b[0]), "r"(b[1]));
}
__device__ __forceinline__ void mma_tf32(float* c, const uint32_t* a, const uint32_t* b) {
    asm volatile("mma.sync.aligned.m16n8k8.row.col.f32.tf32.tf32.f32 "
        "{%0,%1,%2,%3}, {%4,%5,%6,%7}, {%8,%9}, {%0,%1,%2,%3};"
        : "+f"(c[0]), "+f"(c[1]), "+f"(c[2]), "+f"(c[3])
        : "r"(a[0]), "r"(a[1]), "r"(a[2]), "r"(a[3]), "r"(b[0]), "r"(b[1]));
}
__device__ __forceinline__ void ldm_x4_trans(uint32_t* r, uint32_t addr) {
    asm volatile("ldmatrix.sync.aligned.m8n8.x4.trans.shared.b16 {%0,%1,%2,%3}, [%4];"
        : "=r"(r[0]), "=r"(r[1]), "=r"(r[2]), "=r"(r[3]) : "r"(addr));
}
__device__ __forceinline__ uint32_t totf(float x) {
    uint32_t r; asm("cvt.rna.tf32.f32 %0, %1;" : "=r"(r) : "f"(x)); return r;
}
#define PACKBF(r, lo_, hi_) asm("cvt.rn.bf16x2.f32 %0, %1, %2;" : "=r"(r) : "f"(hi_), "f"(lo_))

/* fragment-layout word index (verified R5/R7) */
__host__ __device__ inline int faddr(int k, int n, int npairs) {
    return ((k>>3)*npairs + (n>>4))*128 + ((n&7)*4 + (k&3))*4 + (((n>>3)&1)*2) + ((k>>2)&1);
}
/* A-fragment word index in the global XNf buffer (m rows over MBTOT blocks) */
__device__ __forceinline__ uint32_t gword(int m, int k) {
    return (uint32_t)(((k>>3)*MBTOT + (m>>4))*128 + (m&7)*16 + ((m>>3)&1) + ((k>>2)&1)*2 + (k&3)*4);
}

/* ---------------- scratch ---------------- */
__device__ float    g_X  [(size_t)M2*DIMC];
__device__ uint32_t g_XNf[(size_t)M2*DIMC];   /* LN output, tf32 frag-order */
__device__ uint16_t g_Q [(size_t)M2*INNER];   /* bf16; attn writes O in-place */
__device__ uint16_t g_V [(size_t)M2*INNER];   /* bf16 */
__device__ uint16_t g_H [(size_t)M2*MLPD];    /* bf16 */
__device__ float    g_sdfm[BATCH*DIMC];
__device__ float    g_xmean[BATCH*2*DIMC];
__device__ uint32_t g_Wfrag[(size_t)DEPTH*131072];
#define OFF_QV   0
#define OFF_PROJ 65536
#define OFF_FF1  98304
#define OFF_FF2  114688

/* ---------------- prologue ---------------- */
__global__ void mean_kernel(const float* __restrict__ hsi, const float* __restrict__ lidar) {
    int idx = blockIdx.x*blockDim.x + threadIdx.x;
    if (idx >= BATCH*128) return;
    int b = idx >> 7, c = idx & 127;
    const float* src = (c < 64) ? (hsi + ((size_t)b*64 + c)*NPATCH)
                                : (lidar + ((size_t)b*64 + (c-64))*NPATCH);
    float s = 0.f;
    for (int p = 0; p < NPATCH; p++) s += src[p];
    g_xmean[idx] = s * (1.0f/NPATCH);
}

__global__ void dfm_kernel(const float* __restrict__ fmg_w) {
    int idx = blockIdx.x*blockDim.x + threadIdx.x;
    if (idx >= BATCH*64) return;
    int b = idx >> 6, d = idx & 63;
    const float* xm = g_xmean + b*128;
    const float* wc = fmg_w + d*65;
    float s = 0.f;
    for (int c = 0; c < 128; c++) s += xm[c] * wc[(size_t)c*4096];
    float sig = 1.0f/(1.0f + expf(-s));
    g_sdfm[idx] = sqrtf(sig * SCALEV);
}

__global__ void build_kernel(const float* __restrict__ hsi,
                             const float* __restrict__ cls_hsi, const float* __restrict__ cls_lidar,
                             const float* __restrict__ pos_hsi, const float* __restrict__ pos_lidar) {
    int idx = blockIdx.x*blockDim.x + threadIdx.x;
    if (idx >= M2*DIMC) return;
    int c  = idx & 63;
    int n  = (idx >> 6) % NTOK;
    int bp = idx / (NTOK*64);
    int b  = bp & 63;
    int br = bp >> 6;
    const float* cls = br ? cls_lidar : cls_hsi;
    const float* pos = br ? pos_lidar : pos_hsi;
    float v = (n == 0) ? cls[c] : hsi[((size_t)b*64 + c)*NPATCH + (n-1)];
    g_X[idx] = v + pos[n*64 + c];
}

/* ---------------- layernorm -> frag-order tf32 (phase start only) ---------------- */
__global__ void ln_frag_kernel(const float* __restrict__ Xp,
                               const float* __restrict__ g, const float* __restrict__ bb) {
    int w = threadIdx.x >> 5, lane = threadIdx.x & 31;
    int row = blockIdx.x*8 + w;
    const float* xr = Xp + (size_t)row*64;
    float x0 = xr[lane], x1 = xr[lane+32];
    float s = x0 + x1;
    #pragma unroll
    for (int o = 16; o; o >>= 1) s += __shfl_xor_sync(0xffffffffu, s, o);
    float m = s * (1.0f/64.0f);
    float d0 = x0 - m, d1 = x1 - m;
    float v = d0*d0 + d1*d1;
    #pragma unroll
    for (int o = 16; o; o >>= 1) v += __shfl_xor_sync(0xffffffffu, v, o);
    float r = rsqrtf(v*(1.0f/64.0f) + EPSV);
    g_XNf[gword(row, lane)]      = totf(d0*r*g[lane]    + bb[lane]);
    g_XNf[gword(row, lane+32)]   = totf(d1*r*g[lane+32] + bb[lane+32]);
}

/* ---------------- weight prep (fp32 -> tf32 frag layout) ---------------- */
__global__ void prep_qv(const float* __restrict__ qkv_w) {
    int idx = blockIdx.x*blockDim.x + threadIdx.x;
    if (idx >= DEPTH*64*1024) return;
    int n = idx & 1023, k = (idx >> 10) & 63, L = idx >> 16;
    float v = qkv_w[(size_t)L*64*1536 + k*1536 + (n < 512 ? n : n + 512)];
    g_Wfrag[(size_t)L*131072 + OFF_QV + faddr(k, n, 64)] = totf(v);
}
__global__ void prep_gen(const float* __restrict__ w, int K, int N, int dstoff, int total) {
    int idx = blockIdx.x*blockDim.x + threadIdx.x;
    if (idx >= total) return;
    int kn = K*N;
    int L = idx / kn, rem = idx % kn;
    int k = rem / N, n = rem % N;
    g_Wfrag[(size_t)L*131072 + dstoff + faddr(k, n, N >> 4)] = totf(w[(size_t)idx]);
}

/* ---------------- tf32 mma GEMM v4 ----------------
   AIN: 1 = bf16 A (shift to tf32), 2 = frag-order tf32 A (bulk copy, no cvt).
   OUT: 0 = fp32 C (ACC supported), 1 = bf16 C.
   QV_: dual-output Q/V with sd-scaling folded into Q.
   LNOUT: fused residual+LayerNorm epilogue -> writes g_XNf (needs OUT==0, BN==64==ldc). */
template<int BM, int BN, bool GELU_, bool ACC_, bool BIAS_, bool QV_, int AIN, int OUT, bool LNOUT>
__global__ void __launch_bounds__(256) tgemm(
    const void* __restrict__ Ap, const uint32_t* __restrict__ Bf,
    const float* __restrict__ bias, void* __restrict__ Cp_, void* __restrict__ C2p_,
    const float* __restrict__ lngamma, const float* __restrict__ lnbeta,
    int K, int lda, int Ntot, int ldc)
{
    constexpr int MBLKS = BM/16;
    constexpr int NPB   = BN/16;
    constexpr int MF    = BM/64;
    constexpr int WN    = BN/2;
    constexpr int NF    = WN/8;
    const int NPAIRS = Ntot >> 4;

    extern __shared__ uint32_t dsm[];
    uint32_t* Asm = dsm;                    /* 8*MBLKS*128 words */
    uint32_t* Bsm = dsm + 8*MBLKS*128;      /* 8*NPB*128 words */

    int t = threadIdx.x, lane = t & 31, w = t >> 5;
    int wm = w & 3, wn = w >> 2;
    int m0 = blockIdx.y * BM;
    int n0 = blockIdx.x * BN;
    int np0 = n0 >> 4;

    float acc[MF][NF][4];
    #pragma unroll
    for (int i = 0; i < MF; i++)
        #pragma unroll
        for (int j = 0; j < NF; j++)
            #pragma unroll
            for (int q = 0; q < 4; q++) acc[i][j][q] = 0.f;

    for (int kt = 0; kt < K; kt += 64) {
        /* ---- stage A ---- */
        if (AIN == 1) {
            #pragma unroll
            for (int it = 0; it < BM/32; it++) {
                int idx = t + it*256;
                int m = idx >> 3, k8 = (idx & 7)*8;
                uint4 v = *(const uint4*)((const uint16_t*)Ap + (size_t)(m0+m)*lda + kt + k8);
                const uint16_t* hp = (const uint16_t*)&v;
                int base = ((k8>>3)*MBLKS + (m>>4))*128 + (m&7)*16 + ((m>>3)&1);
                #pragma unroll
                for (int j = 0; j < 8; j++)
                    Asm[base + (j>>2)*2 + (j&3)*4] = ((uint32_t)hp[j]) << 16;
            }
        } else { /* AIN==2: bulk copy from frag-order global */
            const uint4* Afr = (const uint4*)Ap;
            int mb0 = m0 >> 4;
            #pragma unroll
            for (int it = 0; it < MBLKS; it++) {
                int i = t + it*256;
                int kc = i / (MBLKS*32);
                int rem = i % (MBLKS*32);
                ((uint4*)Asm)[i] = __ldg(Afr + (size_t)(kc*MBTOT + mb0 + (rem>>5))*32 + (rem&31));
            }
        }
        /* ---- stage B: bulk copy ---- */
        int kc0 = kt >> 3;
        #pragma unroll
        for (int it = 0; it < NPB; it++) {
            int i = t + it*256;
            int kc = i / (NPB*32);
            int rem = i % (NPB*32);
            int np = rem >> 5, l4 = rem & 31;
            ((uint4*)Bsm)[i] = __ldg((const uint4*)(Bf + (size_t)((kc0+kc)*NPAIRS + np0 + np)*128 + l4*4));
        }
        __syncthreads();

        #pragma unroll
        for (int kc = 0; kc < 8; kc++) {
            uint32_t af[MF][4];
            #pragma unroll
            for (int mf = 0; mf < MF; mf++)
                *(uint4*)af[mf] = *(const uint4*)&Asm[(kc*MBLKS + wm*MF + mf)*128 + lane*4];
            #pragma unroll
            for (int np = 0; np < NF/2; np++) {
                uint4 bv = *(const uint4*)&Bsm[(kc*NPB + wn*(NF/2) + np)*128 + lane*4];
                uint32_t* bf = (uint32_t*)&bv;
                #pragma unroll
                for (int mf = 0; mf < MF; mf++) {
                    mma_tf32(acc[mf][2*np],   af[mf], bf);
                    mma_tf32(acc[mf][2*np+1], af[mf], bf + 2);
                }
            }
        }
        __syncthreads();
    }

    /* ---- epilogue ---- */
    float* rowbuf = (float*)dsm;   /* LNOUT: reuse staging smem, stride 66 */
    int r = lane >> 2, c2 = (lane & 3)*2;
    #pragma unroll
    for (int mf = 0; mf < MF; mf++) {
        int mrow = m0 + wm*(MF*16) + mf*16 + r;
        #pragma unroll
        for (int nf = 0; nf < NF; nf++) {
            int nout = n0 + wn*WN + nf*8 + c2;
            float v00 = acc[mf][nf][0], v01 = acc[mf][nf][1];
            float v10 = acc[mf][nf][2], v11 = acc[mf][nf][3];
            if (BIAS_) {
                float2 bb = *(const float2*)&bias[nout];
                v00 += bb.x; v01 += bb.y; v10 += bb.x; v11 += bb.y;
            }
            if (GELU_) {
                v00 = 0.5f*v00*(1.0f + erff(v00*0.70710678118654752f));
                v01 = 0.5f*v01*(1.0f + erff(v01*0.70710678118654752f));
                v10 = 0.5f*v10*(1.0f + erff(v10*0.70710678118654752f));
                v11 = 0.5f*v11*(1.0f + erff(v11*0.70710678118654752f));
            }
            if (QV_ && nout < 512) {
                int d = nout & 63;
                int b0 = (mrow/NTOK) & 63;
                int b1 = ((mrow+8)/NTOK) & 63;
                float2 s0 = *(const float2*)&g_sdfm[b0*64 + d];
                float2 s1 = *(const float2*)&g_sdfm[b1*64 + d];
                v00 *= s0.x; v01 *= s0.y; v10 *= s1.x; v11 *= s1.y;
            }
            int nc = QV_ ? (nout & 511) : nout;
            if (OUT == 1) {
                uint16_t* dst = (uint16_t*)(QV_ ? (nout < 512 ? Cp_ : C2p_) : Cp_);
                uint32_t pk0, pk1;
                PACKBF(pk0, v00, v01);
                PACKBF(pk1, v10, v11);
                *(uint32_t*)(dst + (size_t)mrow*ldc + nc)     = pk0;
                *(uint32_t*)(dst + (size_t)(mrow+8)*ldc + nc) = pk1;
            } else {
                float* dst = (float*)Cp_;
                float* p0 = dst + (size_t)mrow*ldc + nc;
                float* p1 = dst + (size_t)(mrow+8)*ldc + nc;
                if (ACC_) {
                    float2 o0 = *(float2*)p0, o1 = *(float2*)p1;
                    v00 += o0.x; v01 += o0.y; v10 += o1.x; v11 += o1.y;
                }
                float2 s0; s0.x = v00; s0.y = v01;
                float2 s1; s1.x = v10; s1.y = v11;
                *(float2*)p0 = s0;
                *(float2*)p1 = s1;
                if (LNOUT) {
                    int mr0 = mrow - m0, mr1 = mr0 + 8;
                    rowbuf[mr0*66 + nout]     = v00;
                    rowbuf[mr0*66 + nout + 1] = v01;
                    rowbuf[mr1*66 + nout]     = v10;
                    rowbuf[mr1*66 + nout + 1] = v11;
                }
            }
        }
    }

    if (LNOUT) {
        __syncthreads();
        float lg0 = lngamma[lane], lg1 = lngamma[lane+32];
        float lb0 = lnbeta[lane],  lb1 = lnbeta[lane+32];
        #pragma unroll 1
        for (int i = 0; i < BM/8; i++) {
            int rr = w*(BM/8) + i;
            float x0 = rowbuf[rr*66 + lane], x1 = rowbuf[rr*66 + lane + 32];
            float s = x0 + x1;
            #pragma unroll
            for (int o = 16; o; o >>= 1) s += __shfl_xor_sync(0xffffffffu, s, o);
            float mean = s * (1.0f/64.0f);
            float d0 = x0 - mean, d1 = x1 - mean;
            float vv = d0*d0 + d1*d1;
            #pragma unroll
            for (int o = 16; o; o >>= 1) vv += __shfl_xor_sync(0xffffffffu, vv, o);
            float ri = rsqrtf(vv*(1.0f/64.0f) + EPSV);
            int m = m0 + rr;
            g_XNf[gword(m, lane)]    = totf(d0*ri*lg0 + lb0);
            g_XNf[gword(m, lane+32)] = totf(d1*ri*lg1 + lb1);
        }
    }
}

/* ---------------- bf16 mma.sync fused attention (Q pre-scaled) ---------------- */
#define QSTRIDE 72
#define QBYTES  (256*QSTRIDE*2)
#define ATT_BYTES (2*QBYTES)

__global__ void __launch_bounds__(512) attn_kernel() {
    extern __shared__ char smc[];
    uint16_t* Qh = (uint16_t*)smc;
    uint16_t* Vh = (uint16_t*)(smc + QBYTES);
    uint32_t vbase = smem_u32(smc) + QBYTES;

    int t = threadIdx.x;
    int bh = blockIdx.x;
    int bp = bh >> 3, h = bh & 7;
    uint16_t* Qb = g_Q + (size_t)bp*NTOK*INNER + h*DHEAD;
    const uint16_t* Vb = g_V + (size_t)bp*NTOK*INNER + h*DHEAD;

    /* stage: straight uint4 copies (Q already scaled by QV epilogue) */
    for (int f = t; f < NTOK*8; f += 512) {
        int n = f >> 3, d8 = (f & 7)*8;
        *(uint4*)&Qh[n*QSTRIDE + d8] = *(const uint4*)(Qb + (size_t)n*INNER + d8);
    }
    for (int f = t; f < NTOK*8; f += 512) {
        int n = f >> 3, d8 = (f & 7)*8;
        *(uint4*)&Vh[n*QSTRIDE + d8] = *(const uint4*)(Vb + (size_t)n*INNER + d8);
    }
    {
        uint32_t* qz = (uint32_t*)(Qh + NTOK*QSTRIDE);
        uint32_t* vz = (uint32_t*)(Vh + NTOK*QSTRIDE);
        for (int f = t; f < (256 - NTOK)*QSTRIDE/2; f += 512) { qz[f] = 0u; vz[f] = 0u; }
    }
    __syncthreads();

    int lane = t & 31;
    int wid  = t >> 5;
    int m0   = wid*16;
    int r    = lane >> 2;
    int c2   = (lane & 3)*2;

    uint32_t qa[4][4];
    #pragma unroll
    for (int kb = 0; kb < 4; kb++) {
        const uint16_t* qrow = Qh + (m0 + r)*QSTRIDE + kb*16 + c2;
        qa[kb][0] = *(const uint32_t*)(qrow);
        qa[kb][1] = *(const uint32_t*)(qrow + 8*QSTRIDE);
        qa[kb][2] = *(const uint32_t*)(qrow + 8);
        qa[kb][3] = *(const uint32_t*)(qrow + 8*QSTRIDE + 8);
    }

    float O[8][4];
    #pragma unroll
    for (int nt = 0; nt < 8; nt++)
        #pragma unroll
        for (int j = 0; j < 4; j++) O[nt][j] = 0.f;
    float rs0 = 0.f, rs1 = 0.f;

    for (int ch = 0; ch < 4; ch++) {
        float S[8][4];
        #pragma unroll
        for (int nt = 0; nt < 8; nt++)
            #pragma unroll
            for (int j = 0; j < 4; j++) S[nt][j] = 0.f;
        #pragma unroll
        for (int kb = 0; kb < 4; kb++) {
            #pragma unroll
            for (int nt = 0; nt < 8; nt++) {
                const uint16_t* brow = Qh + (ch*64 + nt*8 + r)*QSTRIDE + kb*16 + c2;
                uint32_t b[2] = { *(const uint32_t*)brow, *(const uint32_t*)(brow + 8) };
                mma_bf16(S[nt], qa[kb], b);
            }
        }
        uint32_t pa[4][4];
        #pragma unroll
        for (int nt = 0; nt < 8; nt++) {
            int col = ch*64 + nt*8 + c2;
            float e0 = (col     < NTOK) ? __expf(S[nt][0]) : 0.f;
            float e1 = (col + 1 < NTOK) ? __expf(S[nt][1]) : 0.f;
            float e2 = (col     < NTOK) ? __expf(S[nt][2]) : 0.f;
            float e3 = (col + 1 < NTOK) ? __expf(S[nt][3]) : 0.f;
            rs0 += e0 + e1;
            rs1 += e2 + e3;
            uint32_t plo, phi;
            PACKBF(plo, e0, e1);
            PACKBF(phi, e2, e3);
            pa[nt >> 1][(nt & 1)*2]     = plo;
            pa[nt >> 1][(nt & 1)*2 + 1] = phi;
        }
        #pragma unroll
        for (int kb = 0; kb < 4; kb++) {
            uint32_t vb[16];
            int krow = ch*64 + kb*16 + (lane & 15);
            int coff = 8*(lane >> 4);
            #pragma unroll
            for (int q = 0; q < 4; q++)
                ldm_x4_trans(vb + q*4, vbase + (uint32_t)(krow*QSTRIDE + q*16 + coff)*2);
            #pragma unroll
            for (int nt = 0; nt < 8; nt++)
                mma_bf16(O[nt], pa[kb], &vb[(nt >> 1)*4 + (nt & 1)*2]);
        }
    }

    #pragma unroll
    for (int o = 1; o <= 2; o <<= 1) {
        rs0 += __shfl_xor_sync(0xffffffffu, rs0, o);
        rs1 += __shfl_xor_sync(0xffffffffu, rs1, o);
    }
    float ri0 = 1.0f/rs0, ri1 = 1.0f/rs1;
    int i0 = m0 + r;
    if (i0 < NTOK) {
        uint16_t* op = Qb + (size_t)i0*INNER;
        #pragma unroll
        for (int nt = 0; nt < 8; nt++) {
            uint32_t pk;
            PACKBF(pk, O[nt][0]*ri0, O[nt][1]*ri0);
            *(uint32_t*)(op + nt*8 + c2) = pk;
        }
    }
    if (i0 + 8 < NTOK) {
        uint16_t* op = Qb + (size_t)(i0 + 8)*INNER;
        #pragma unroll
        for (int nt = 0; nt < 8; nt++) {
            uint32_t pk;
            PACKBF(pk, O[nt][2]*ri1, O[nt][3]*ri1);
            *(uint32_t*)(op + nt*8 + c2) = pk;
        }
    }
}

/* ---------------- token exchange (X + XNf) + final ---------------- */
__global__ void swap_cls_kernel() {
    int idx = blockIdx.x*blockDim.x + threadIdx.x;
    if (idx >= BATCH*64) return;
    int b = idx >> 6, c = idx & 63;
    int m0_ = b*NTOK, m1_ = (b+BATCH)*NTOK;
    size_t i0 = (size_t)m0_*64 + c;
    size_t i1 = (size_t)m1_*64 + c;
    float a = g_X[i0], d = g_X[i1];
    g_X[i0] = d; g_X[i1] = a;
    uint32_t w0 = gword(m0_, c), w1 = gword(m1_, c);
    uint32_t u = g_XNf[w0], v = g_XNf[w1];
    g_XNf[w0] = v; g_XNf[w1] = u;
}

__global__ void final_kernel(float* __restrict__ out) {
    int idx = blockIdx.x*blockDim.x + threadIdx.x;
    if (idx >= BATCH*64) return;
    int b = idx >> 6, c = idx & 63;
    out[idx] = g_X[(size_t)b*NTOK*64 + c] + g_X[(size_t)(b+BATCH)*NTOK*64 + c];
}

/* ---------------- host ---------------- */
extern "C" void kernel_launch(void* const* d_in, const int* in_sizes, int n_in,
                              void* d_out, int out_size)
{
    const float* hsi       = (const float*)d_in[0];
    const float* lidar     = (const float*)d_in[1];
    const float* cls_hsi   = (const float*)d_in[2];
    const float* cls_lidar = (const float*)d_in[3];
    const float* pos_hsi   = (const float*)d_in[4];
    const float* pos_lidar = (const float*)d_in[5];
    const float* fmg_w     = (const float*)d_in[6];
    const float* ln1_g     = (const float*)d_in[7];
    const float* ln1_b     = (const float*)d_in[8];
    const float* qkv_w     = (const float*)d_in[9];
    const float* out_w     = (const float*)d_in[10];
    const float* out_b     = (const float*)d_in[11];
    const float* ln2_g     = (const float*)d_in[12];
    const float* ln2_b     = (const float*)d_in[13];
    const float* ff_w1     = (const float*)d_in[14];
    const float* ff_b1     = (const float*)d_in[15];
    const float* ff_w2     = (const float*)d_in[16];
    const float* ff_b2     = (const float*)d_in[17];

    float *X;
    uint32_t *XNf, *Wf;
    uint16_t *Qb, *Vb, *Hb;
    cudaGetSymbolAddress((void**)&X,   g_X);
    cudaGetSymbolAddress((void**)&XNf, g_XNf);
    cudaGetSymbolAddress((void**)&Qb,  g_Q);
    cudaGetSymbolAddress((void**)&Vb,  g_V);
    cudaGetSymbolAddress((void**)&Hb,  g_H);
    cudaGetSymbolAddress((void**)&Wf,  g_Wfrag);

    cudaFuncSetAttribute(attn_kernel, cudaFuncAttributeMaxDynamicSharedMemorySize, ATT_BYTES);
    cudaFuncSetAttribute(tgemm<128,128,false,false,false,true,2,1,false>,
                         cudaFuncAttributeMaxDynamicSharedMemorySize, 65536);
    cudaFuncSetAttribute(tgemm<128,128,true,false,true,false,2,1,false>,
                         cudaFuncAttributeMaxDynamicSharedMemorySize, 65536);
    cudaFuncSetAttribute(tgemm<64,64,false,true,true,false,1,0,true>,
                         cudaFuncAttributeMaxDynamicSharedMemorySize, 32768);

    mean_kernel<<<32, 256>>>(hsi, lidar);
    dfm_kernel<<<16, 256>>>(fmg_w);
    build_kernel<<<(M2*DIMC + 255)/256, 256>>>(hsi, cls_hsi, cls_lidar, pos_hsi, pos_lidar);
    ln_frag_kernel<<<M2/8, 256>>>(X, ln1_g, ln1_b);

    prep_qv<<<DEPTH*64*1024/256, 256>>>(qkv_w);
    prep_gen<<<DEPTH*512*64/256, 256>>>(out_w, 512, 64, OFF_PROJ, DEPTH*512*64);
    prep_gen<<<DEPTH*64*256/256, 256>>>(ff_w1, 64, 256, OFF_FF1, DEPTH*64*256);
    prep_gen<<<DEPTH*256*64/256, 256>>>(ff_w2, 256, 64, OFF_FF2, DEPTH*256*64);

    for (int phase = 0; phase < 2; phase++) {
        for (int L = 0; L < DEPTH; L++) {
            const uint32_t* WL = Wf + (size_t)L*131072;
            int Ln = (L + 1) & 3;
            /* QV (A = XNf frag, Q scaled by sd in epilogue) */
            tgemm<128,128,false,false,false,true,2,1,false><<<dim3(8,226), 256, 65536>>>(
                XNf, WL + OFF_QV, nullptr, Qb, Vb, nullptr, nullptr, 64, 0, 1024, 512);
            attn_kernel<<<1024, 512, ATT_BYTES>>>();
            /* proj + residual + fused LN2 -> XNf */
            tgemm<64,64,false,true,true,false,1,0,true><<<dim3(1,452), 256, 32768>>>(
                Qb, WL + OFF_PROJ, out_b + L*64, X, nullptr,
                ln2_g + L*64, ln2_b + L*64, 512, 512, 64, 64);
            /* ff1 (A = XNf frag) + GELU */
            tgemm<128,128,true,false,true,false,2,1,false><<<dim3(2,226), 256, 65536>>>(
                XNf, WL + OFF_FF1, ff_b1 + L*256, Hb, nullptr, nullptr, nullptr, 64, 0, 256, 256);
            /* ff2 + residual + fused LN1(next layer) -> XNf */
            tgemm<64,64,false,true,true,false,1,0,true><<<dim3(1,452), 256, 32768>>>(
                Hb, WL + OFF_FF2, ff_b2 + L*64, X, nullptr,
                ln1_g + Ln*64, ln1_b + Ln*64, 256, 256, 64, 64);
        }
        if (phase == 0) swap_cls_kernel<<<16, 256>>>();
    }
    final_kernel<<<16, 256>>>((float*)d_out);
}

// round 11
// speedup vs baseline: 1.0025x; 1.0025x over previous
#include <cuda_runtime.h>
#include <cuda_bf16.h>
#include <math.h>
#include <cstdint>

#define BATCH   64
#define DIMC    64
#define HEADS   8
#define DHEAD   64
#define INNER   512
#define MLPD    256
#define DEPTH   4
#define NPATCH  225
#define NTOK    226
#define M2      (2*BATCH*NTOK)   /* 28928 rows */
#define MBTOT   (M2/16)          /* 1808 m-blocks */
#define EPSV    1e-5f
#define SCALEV  0.125f

/* ---------------- mma helpers ---------------- */
__device__ __forceinline__ uint32_t smem_u32(const void* p) {
    uint32_t a;
    asm("{ .reg .u64 t; cvta.to.shared.u64 t, %1; cvt.u32.u64 %0, t; }" : "=r"(a) : "l"(p));
    return a;
}
__device__ __forceinline__ void mma_bf16(float* c, const uint32_t* a, const uint32_t* b) {
    asm volatile("mma.sync.aligned.m16n8k16.row.col.f32.bf16.bf16.f32 "
        "{%0,%1,%2,%3}, {%4,%5,%6,%7}, {%8,%9}, {%0,%1,%2,%3};"
        : "+f"(c[0]), "+f"(c[1]), "+f"(c[2]), "+f"(c[3])
        : "r"(a[0]), "r"(a[1]), "r"(a[2]), "r"(a[3]), "r"(b[0]), "r"(b[1]));
}
__device__ __forceinline__ void mma_tf32(float* c, const uint32_t* a, const uint32_t* b) {
    asm volatile("mma.sync.aligned.m16n8k8.row.col.f32.tf32.tf32.f32 "
        "{%0,%1,%2,%3}, {%4,%5,%6,%7}, {%8,%9}, {%0,%1,%2,%3};"
        : "+f"(c[0]), "+f"(c[1]), "+f"(c[2]), "+f"(c[3])
        : "r"(a[0]), "r"(a[1]), "r"(a[2]), "r"(a[3]), "r"(b[0]), "r"(b[1]));
}
__device__ __forceinline__ void ldm_x4_trans(uint32_t* r, uint32_t addr) {
    asm volatile("ldmatrix.sync.aligned.m8n8.x4.trans.shared.b16 {%0,%1,%2,%3}, [%4];"
        : "=r"(r[0]), "=r"(r[1]), "=r"(r[2]), "=r"(r[3]) : "r"(addr));
}
__device__ __forceinline__ uint32_t totf(float x) {
    uint32_t r; asm("cvt.rna.tf32.f32 %0, %1;" : "=r"(r) : "f"(x)); return r;
}
#define PACKBF(r, lo_, hi_) asm("cvt.rn.bf16x2.f32 %0, %1, %2;" : "=r"(r) : "f"(hi_), "f"(lo_))

/* fragment-layout word index (verified R5/R7) */
__host__ __device__ inline int faddr(int k, int n, int npairs) {
    return ((k>>3)*npairs + (n>>4))*128 + ((n&7)*4 + (k&3))*4 + (((n>>3)&1)*2) + ((k>>2)&1);
}
/* A-fragment word index in the global XNf buffer (m rows over MBTOT blocks) */
__device__ __forceinline__ uint32_t gword(int m, int k) {
    return (uint32_t)(((k>>3)*MBTOT + (m>>4))*128 + (m&7)*16 + ((m>>3)&1) + ((k>>2)&1)*2 + (k&3)*4);
}

/* ---------------- scratch ---------------- */
__device__ float    g_X  [(size_t)M2*DIMC];
__device__ uint32_t g_XNf[(size_t)M2*DIMC];   /* LN output, tf32 frag-order */
__device__ uint16_t g_Q [(size_t)M2*INNER];   /* bf16; attn writes O in-place */
__device__ uint16_t g_V [(size_t)M2*INNER];   /* bf16 */
__device__ uint16_t g_H [(size_t)M2*MLPD];    /* bf16 */
__device__ float    g_sdfm[BATCH*DIMC];
__device__ float    g_xmean[BATCH*2*DIMC];
__device__ uint32_t g_Wfrag[(size_t)DEPTH*131072];
#define OFF_QV   0
#define OFF_PROJ 65536
#define OFF_FF1  98304
#define OFF_FF2  114688

/* ---------------- prologue ---------------- */
__global__ void mean_kernel(const float* __restrict__ hsi, const float* __restrict__ lidar) {
    int idx = blockIdx.x*blockDim.x + threadIdx.x;
    if (idx >= BATCH*128) return;
    int b = idx >> 7, c = idx & 127;
    const float* src = (c < 64) ? (hsi + ((size_t)b*64 + c)*NPATCH)
                                : (lidar + ((size_t)b*64 + (c-64))*NPATCH);
    float s = 0.f;
    for (int p = 0; p < NPATCH; p++) s += src[p];
    g_xmean[idx] = s * (1.0f/NPATCH);
}

__global__ void dfm_kernel(const float* __restrict__ fmg_w) {
    int idx = blockIdx.x*blockDim.x + threadIdx.x;
    if (idx >= BATCH*64) return;
    int b = idx >> 6, d = idx & 63;
    const float* xm = g_xmean + b*128;
    const float* wc = fmg_w + d*65;
    float s = 0.f;
    for (int c = 0; c < 128; c++) s += xm[c] * wc[(size_t)c*4096];
    float sig = 1.0f/(1.0f + expf(-s));
    g_sdfm[idx] = sqrtf(sig * SCALEV);
}

__global__ void build_kernel(const float* __restrict__ hsi,
                             const float* __restrict__ cls_hsi, const float* __restrict__ cls_lidar,
                             const float* __restrict__ pos_hsi, const float* __restrict__ pos_lidar) {
    int idx = blockIdx.x*blockDim.x + threadIdx.x;
    if (idx >= M2*DIMC) return;
    int c  = idx & 63;
    int n  = (idx >> 6) % NTOK;
    int bp = idx / (NTOK*64);
    int b  = bp & 63;
    int br = bp >> 6;
    const float* cls = br ? cls_lidar : cls_hsi;
    const float* pos = br ? pos_lidar : pos_hsi;
    float v = (n == 0) ? cls[c] : hsi[((size_t)b*64 + c)*NPATCH + (n-1)];
    g_X[idx] = v + pos[n*64 + c];
}

/* ---------------- layernorm -> frag-order tf32 (phase start only) ---------------- */
__global__ void ln_frag_kernel(const float* __restrict__ Xp,
                               const float* __restrict__ g, const float* __restrict__ bb) {
    int w = threadIdx.x >> 5, lane = threadIdx.x & 31;
    int row = blockIdx.x*8 + w;
    const float* xr = Xp + (size_t)row*64;
    float x0 = xr[lane], x1 = xr[lane+32];
    float s = x0 + x1;
    #pragma unroll
    for (int o = 16; o; o >>= 1) s += __shfl_xor_sync(0xffffffffu, s, o);
    float m = s * (1.0f/64.0f);
    float d0 = x0 - m, d1 = x1 - m;
    float v = d0*d0 + d1*d1;
    #pragma unroll
    for (int o = 16; o; o >>= 1) v += __shfl_xor_sync(0xffffffffu, v, o);
    float r = rsqrtf(v*(1.0f/64.0f) + EPSV);
    g_XNf[gword(row, lane)]      = totf(d0*r*g[lane]    + bb[lane]);
    g_XNf[gword(row, lane+32)]   = totf(d1*r*g[lane+32] + bb[lane+32]);
}

/* ---------------- weight prep (fp32 -> tf32 frag layout) ---------------- */
__global__ void prep_qv(const float* __restrict__ qkv_w) {
    int idx = blockIdx.x*blockDim.x + threadIdx.x;
    if (idx >= DEPTH*64*1024) return;
    int n = idx & 1023, k = (idx >> 10) & 63, L = idx >> 16;
    float v = qkv_w[(size_t)L*64*1536 + k*1536 + (n < 512 ? n : n + 512)];
    g_Wfrag[(size_t)L*131072 + OFF_QV + faddr(k, n, 64)] = totf(v);
}
__global__ void prep_gen(const float* __restrict__ w, int K, int N, int dstoff, int total) {
    int idx = blockIdx.x*blockDim.x + threadIdx.x;
    if (idx >= total) return;
    int kn = K*N;
    int L = idx / kn, rem = idx % kn;
    int k = rem / N, n = rem % N;
    g_Wfrag[(size_t)L*131072 + dstoff + faddr(k, n, N >> 4)] = totf(w[(size_t)idx]);
}

/* ---------------- tf32 mma GEMM v4 ----------------
   AIN: 1 = bf16 A (shift to tf32), 2 = frag-order tf32 A (bulk copy, no cvt).
   OUT: 0 = fp32 C (ACC supported), 1 = bf16 C.
   QV_: dual-output Q/V with sd-scaling folded into Q.
   LNOUT: fused residual+LayerNorm epilogue -> writes g_XNf (needs OUT==0, BN==64==ldc). */
template<int BM, int BN, bool GELU_, bool ACC_, bool BIAS_, bool QV_, int AIN, int OUT, bool LNOUT>
__global__ void __launch_bounds__(256) tgemm(
    const void* __restrict__ Ap, const uint32_t* __restrict__ Bf,
    const float* __restrict__ bias, void* __restrict__ Cp_, void* __restrict__ C2p_,
    const float* __restrict__ lngamma, const float* __restrict__ lnbeta,
    int K, int lda, int Ntot, int ldc)
{
    constexpr int MBLKS = BM/16;
    constexpr int NPB   = BN/16;
    constexpr int MF    = BM/64;
    constexpr int WN    = BN/2;
    constexpr int NF    = WN/8;
    const int NPAIRS = Ntot >> 4;

    extern __shared__ uint32_t dsm[];
    uint32_t* Asm = dsm;                    /* 8*MBLKS*128 words */
    uint32_t* Bsm = dsm + 8*MBLKS*128;      /* 8*NPB*128 words */

    int t = threadIdx.x, lane = t & 31, w = t >> 5;
    int wm = w & 3, wn = w >> 2;
    int m0 = blockIdx.y * BM;
    int n0 = blockIdx.x * BN;
    int np0 = n0 >> 4;

    float acc[MF][NF][4];
    #pragma unroll
    for (int i = 0; i < MF; i++)
        #pragma unroll
        for (int j = 0; j < NF; j++)
            #pragma unroll
            for (int q = 0; q < 4; q++) acc[i][j][q] = 0.f;

    for (int kt = 0; kt < K; kt += 64) {
        /* ---- stage A ---- */
        if (AIN == 1) {
            #pragma unroll
            for (int it = 0; it < BM/32; it++) {
                int idx = t + it*256;
                int m = idx >> 3, k8 = (idx & 7)*8;
                uint4 v = *(const uint4*)((const uint16_t*)Ap + (size_t)(m0+m)*lda + kt + k8);
                const uint16_t* hp = (const uint16_t*)&v;
                int base = ((k8>>3)*MBLKS + (m>>4))*128 + (m&7)*16 + ((m>>3)&1);
                #pragma unroll
                for (int j = 0; j < 8; j++)
                    Asm[base + (j>>2)*2 + (j&3)*4] = ((uint32_t)hp[j]) << 16;
            }
        } else { /* AIN==2: bulk copy from frag-order global */
            const uint4* Afr = (const uint4*)Ap;
            int mb0 = m0 >> 4;
            #pragma unroll
            for (int it = 0; it < MBLKS; it++) {
                int i = t + it*256;
                int kc = i / (MBLKS*32);
                int rem = i % (MBLKS*32);
                ((uint4*)Asm)[i] = __ldg(Afr + (size_t)(kc*MBTOT + mb0 + (rem>>5))*32 + (rem&31));
            }
        }
        /* ---- stage B: bulk copy ---- */
        int kc0 = kt >> 3;
        #pragma unroll
        for (int it = 0; it < NPB; it++) {
            int i = t + it*256;
            int kc = i / (NPB*32);
            int rem = i % (NPB*32);
            int np = rem >> 5, l4 = rem & 31;
            ((uint4*)Bsm)[i] = __ldg((const uint4*)(Bf + (size_t)((kc0+kc)*NPAIRS + np0 + np)*128 + l4*4));
        }
        __syncthreads();

        #pragma unroll
        for (int kc = 0; kc < 8; kc++) {
            uint32_t af[MF][4];
            #pragma unroll
            for (int mf = 0; mf < MF; mf++)
                *(uint4*)af[mf] = *(const uint4*)&Asm[(kc*MBLKS + wm*MF + mf)*128 + lane*4];
            #pragma unroll
            for (int np = 0; np < NF/2; np++) {
                uint4 bv = *(const uint4*)&Bsm[(kc*NPB + wn*(NF/2) + np)*128 + lane*4];
                uint32_t* bf = (uint32_t*)&bv;
                #pragma unroll
                for (int mf = 0; mf < MF; mf++) {
                    mma_tf32(acc[mf][2*np],   af[mf], bf);
                    mma_tf32(acc[mf][2*np+1], af[mf], bf + 2);
                }
            }
        }
        __syncthreads();
    }

    /* ---- epilogue ---- */
    float* rowbuf = (float*)dsm;   /* LNOUT: reuse staging smem, stride 66 */
    int r = lane >> 2, c2 = (lane & 3)*2;
    #pragma unroll
    for (int mf = 0; mf < MF; mf++) {
        int mrow = m0 + wm*(MF*16) + mf*16 + r;
        #pragma unroll
        for (int nf = 0; nf < NF; nf++) {
            int nout = n0 + wn*WN + nf*8 + c2;
            float v00 = acc[mf][nf][0], v01 = acc[mf][nf][1];
            float v10 = acc[mf][nf][2], v11 = acc[mf][nf][3];
            if (BIAS_) {
                float2 bb = *(const float2*)&bias[nout];
                v00 += bb.x; v01 += bb.y; v10 += bb.x; v11 += bb.y;
            }
            if (GELU_) {
                v00 = 0.5f*v00*(1.0f + erff(v00*0.70710678118654752f));
                v01 = 0.5f*v01*(1.0f + erff(v01*0.70710678118654752f));
                v10 = 0.5f*v10*(1.0f + erff(v10*0.70710678118654752f));
                v11 = 0.5f*v11*(1.0f + erff(v11*0.70710678118654752f));
            }
            if (QV_ && nout < 512) {
                int d = nout & 63;
                int b0 = (mrow/NTOK) & 63;
                int b1 = ((mrow+8)/NTOK) & 63;
                float2 s0 = *(const float2*)&g_sdfm[b0*64 + d];
                float2 s1 = *(const float2*)&g_sdfm[b1*64 + d];
                v00 *= s0.x; v01 *= s0.y; v10 *= s1.x; v11 *= s1.y;
            }
            int nc = QV_ ? (nout & 511) : nout;
            if (OUT == 1) {
                uint16_t* dst = (uint16_t*)(QV_ ? (nout < 512 ? Cp_ : C2p_) : Cp_);
                uint32_t pk0, pk1;
                PACKBF(pk0, v00, v01);
                PACKBF(pk1, v10, v11);
                *(uint32_t*)(dst + (size_t)mrow*ldc + nc)     = pk0;
                *(uint32_t*)(dst + (size_t)(mrow+8)*ldc + nc) = pk1;
            } else {
                float* dst = (float*)Cp_;
                float* p0 = dst + (size_t)mrow*ldc + nc;
                float* p1 = dst + (size_t)(mrow+8)*ldc + nc;
                if (ACC_) {
                    float2 o0 = *(float2*)p0, o1 = *(float2*)p1;
                    v00 += o0.x; v01 += o0.y; v10 += o1.x; v11 += o1.y;
                }
                float2 s0; s0.x = v00; s0.y = v01;
                float2 s1; s1.x = v10; s1.y = v11;
                *(float2*)p0 = s0;
                *(float2*)p1 = s1;
                if (LNOUT) {
                    int mr0 = mrow - m0, mr1 = mr0 + 8;
                    rowbuf[mr0*66 + nout]     = v00;
                    rowbuf[mr0*66 + nout + 1] = v01;
                    rowbuf[mr1*66 + nout]     = v10;
                    rowbuf[mr1*66 + nout + 1] = v11;
                }
            }
        }
    }

    if (LNOUT) {
        __syncthreads();
        float lg0 = lngamma[lane], lg1 = lngamma[lane+32];
        float lb0 = lnbeta[lane],  lb1 = lnbeta[lane+32];
        #pragma unroll 1
        for (int i = 0; i < BM/8; i++) {
            int rr = w*(BM/8) + i;
            float x0 = rowbuf[rr*66 + lane], x1 = rowbuf[rr*66 + lane + 32];
            float s = x0 + x1;
            #pragma unroll
            for (int o = 16; o; o >>= 1) s += __shfl_xor_sync(0xffffffffu, s, o);
            float mean = s * (1.0f/64.0f);
            float d0 = x0 - mean, d1 = x1 - mean;
            float vv = d0*d0 + d1*d1;
            #pragma unroll
            for (int o = 16; o; o >>= 1) vv += __shfl_xor_sync(0xffffffffu, vv, o);
            float ri = rsqrtf(vv*(1.0f/64.0f) + EPSV);
            int m = m0 + rr;
            g_XNf[gword(m, lane)]    = totf(d0*ri*lg0 + lb0);
            g_XNf[gword(m, lane+32)] = totf(d1*ri*lg1 + lb1);
        }
    }
}

/* ---------------- bf16 mma.sync fused attention (Q pre-scaled) ---------------- */
#define QSTRIDE 72
#define QBYTES  (256*QSTRIDE*2)
#define ATT_BYTES (2*QBYTES)

__global__ void __launch_bounds__(512) attn_kernel() {
    extern __shared__ char smc[];
    uint16_t* Qh = (uint16_t*)smc;
    uint16_t* Vh = (uint16_t*)(smc + QBYTES);
    uint32_t vbase = smem_u32(smc) + QBYTES;

    int t = threadIdx.x;
    int bh = blockIdx.x;
    int bp = bh >> 3, h = bh & 7;
    uint16_t* Qb = g_Q + (size_t)bp*NTOK*INNER + h*DHEAD;
    const uint16_t* Vb = g_V + (size_t)bp*NTOK*INNER + h*DHEAD;

    /* stage: straight uint4 copies (Q already scaled by QV epilogue) */
    for (int f = t; f < NTOK*8; f += 512) {
        int n = f >> 3, d8 = (f & 7)*8;
        *(uint4*)&Qh[n*QSTRIDE + d8] = *(const uint4*)(Qb + (size_t)n*INNER + d8);
    }
    for (int f = t; f < NTOK*8; f += 512) {
        int n = f >> 3, d8 = (f & 7)*8;
        *(uint4*)&Vh[n*QSTRIDE + d8] = *(const uint4*)(Vb + (size_t)n*INNER + d8);
    }
    {
        uint32_t* qz = (uint32_t*)(Qh + NTOK*QSTRIDE);
        uint32_t* vz = (uint32_t*)(Vh + NTOK*QSTRIDE);
        for (int f = t; f < (256 - NTOK)*QSTRIDE/2; f += 512) { qz[f] = 0u; vz[f] = 0u; }
    }
    __syncthreads();

    int lane = t & 31;
    int wid  = t >> 5;
    int m0   = wid*16;
    int r    = lane >> 2;
    int c2   = (lane & 3)*2;

    uint32_t qa[4][4];
    #pragma unroll
    for (int kb = 0; kb < 4; kb++) {
        const uint16_t* qrow = Qh + (m0 + r)*QSTRIDE + kb*16 + c2;
        qa[kb][0] = *(const uint32_t*)(qrow);
        qa[kb][1] = *(const uint32_t*)(qrow + 8*QSTRIDE);
        qa[kb][2] = *(const uint32_t*)(qrow + 8);
        qa[kb][3] = *(const uint32_t*)(qrow + 8*QSTRIDE + 8);
    }

    float O[8][4];
    #pragma unroll
    for (int nt = 0; nt < 8; nt++)
        #pragma unroll
        for (int j = 0; j < 4; j++) O[nt][j] = 0.f;
    float rs0 = 0.f, rs1 = 0.f;

    for (int ch = 0; ch < 4; ch++) {
        float S[8][4];
        #pragma unroll
        for (int nt = 0; nt < 8; nt++)
            #pragma unroll
            for (int j = 0; j < 4; j++) S[nt][j] = 0.f;
        #pragma unroll
        for (int kb = 0; kb < 4; kb++) {
            #pragma unroll
            for (int nt = 0; nt < 8; nt++) {
                const uint16_t* brow = Qh + (ch*64 + nt*8 + r)*QSTRIDE + kb*16 + c2;
                uint32_t b[2] = { *(const uint32_t*)brow, *(const uint32_t*)(brow + 8) };
                mma_bf16(S[nt], qa[kb], b);
            }
        }
        uint32_t pa[4][4];
        #pragma unroll
        for (int nt = 0; nt < 8; nt++) {
            int col = ch*64 + nt*8 + c2;
            float e0 = (col     < NTOK) ? __expf(S[nt][0]) : 0.f;
            float e1 = (col + 1 < NTOK) ? __expf(S[nt][1]) : 0.f;
            float e2 = (col     < NTOK) ? __expf(S[nt][2]) : 0.f;
            float e3 = (col + 1 < NTOK) ? __expf(S[nt][3]) : 0.f;
            rs0 += e0 + e1;
            rs1 += e2 + e3;
            uint32_t plo, phi;
            PACKBF(plo, e0, e1);
            PACKBF(phi, e2, e3);
            pa[nt >> 1][(nt & 1)*2]     = plo;
            pa[nt >> 1][(nt & 1)*2 + 1] = phi;
        }
        #pragma unroll
        for (int kb = 0; kb < 4; kb++) {
            uint32_t vb[16];
            int krow = ch*64 + kb*16 + (lane & 15);
            int coff = 8*(lane >> 4);
            #pragma unroll
            for (int q = 0; q < 4; q++)
                ldm_x4_trans(vb + q*4, vbase + (uint32_t)(krow*QSTRIDE + q*16 + coff)*2);
            #pragma unroll
            for (int nt = 0; nt < 8; nt++)
                mma_bf16(O[nt], pa[kb], &vb[(nt >> 1)*4 + (nt & 1)*2]);
        }
    }

    #pragma unroll
    for (int o = 1; o <= 2; o <<= 1) {
        rs0 += __shfl_xor_sync(0xffffffffu, rs0, o);
        rs1 += __shfl_xor_sync(0xffffffffu, rs1, o);
    }
    float ri0 = 1.0f/rs0, ri1 = 1.0f/rs1;
    int i0 = m0 + r;
    if (i0 < NTOK) {
        uint16_t* op = Qb + (size_t)i0*INNER;
        #pragma unroll
        for (int nt = 0; nt < 8; nt++) {
            uint32_t pk;
            PACKBF(pk, O[nt][0]*ri0, O[nt][1]*ri0);
            *(uint32_t*)(op + nt*8 + c2) = pk;
        }
    }
    if (i0 + 8 < NTOK) {
        uint16_t* op = Qb + (size_t)(i0 + 8)*INNER;
        #pragma unroll
        for (int nt = 0; nt < 8; nt++) {
            uint32_t pk;
            PACKBF(pk, O[nt][2]*ri1, O[nt][3]*ri1);
            *(uint32_t*)(op + nt*8 + c2) = pk;
        }
    }
}

/* ---------------- token exchange (X + XNf) + final ---------------- */
__global__ void swap_cls_kernel() {
    int idx = blockIdx.x*blockDim.x + threadIdx.x;
    if (idx >= BATCH*64) return;
    int b = idx >> 6, c = idx & 63;
    int m0_ = b*NTOK, m1_ = (b+BATCH)*NTOK;
    size_t i0 = (size_t)m0_*64 + c;
    size_t i1 = (size_t)m1_*64 + c;
    float a = g_X[i0], d = g_X[i1];
    g_X[i0] = d; g_X[i1] = a;
    uint32_t w0 = gword(m0_, c), w1 = gword(m1_, c);
    uint32_t u = g_XNf[w0], v = g_XNf[w1];
    g_XNf[w0] = v; g_XNf[w1] = u;
}

__global__ void final_kernel(float* __restrict__ out) {
    int idx = blockIdx.x*blockDim.x + threadIdx.x;
    if (idx >= BATCH*64) return;
    int b = idx >> 6, c = idx & 63;
    out[idx] = g_X[(size_t)b*NTOK*64 + c] + g_X[(size_t)(b+BATCH)*NTOK*64 + c];
}

/* ---------------- host ---------------- */
extern "C" void kernel_launch(void* const* d_in, const int* in_sizes, int n_in,
                              void* d_out, int out_size)
{
    const float* hsi       = (const float*)d_in[0];
    const float* lidar     = (const float*)d_in[1];
    const float* cls_hsi   = (const float*)d_in[2];
    const float* cls_lidar = (const float*)d_in[3];
    const float* pos_hsi   = (const float*)d_in[4];
    const float* pos_lidar = (const float*)d_in[5];
    const float* fmg_w     = (const float*)d_in[6];
    const float* ln1_g     = (const float*)d_in[7];
    const float* ln1_b     = (const float*)d_in[8];
    const float* qkv_w     = (const float*)d_in[9];
    const float* out_w     = (const float*)d_in[10];
    const float* out_b     = (const float*)d_in[11];
    const float* ln2_g     = (const float*)d_in[12];
    const float* ln2_b     = (const float*)d_in[13];
    const float* ff_w1     = (const float*)d_in[14];
    const float* ff_b1     = (const float*)d_in[15];
    const float* ff_w2     = (const float*)d_in[16];
    const float* ff_b2     = (const float*)d_in[17];

    float *X;
    uint32_t *XNf, *Wf;
    uint16_t *Qb, *Vb, *Hb;
    cudaGetSymbolAddress((void**)&X,   g_X);
    cudaGetSymbolAddress((void**)&XNf, g_XNf);
    cudaGetSymbolAddress((void**)&Qb,  g_Q);
    cudaGetSymbolAddress((void**)&Vb,  g_V);
    cudaGetSymbolAddress((void**)&Hb,  g_H);
    cudaGetSymbolAddress((void**)&Wf,  g_Wfrag);

    cudaFuncSetAttribute(attn_kernel, cudaFuncAttributeMaxDynamicSharedMemorySize, ATT_BYTES);
    cudaFuncSetAttribute(tgemm<128,128,false,false,false,true,2,1,false>,
                         cudaFuncAttributeMaxDynamicSharedMemorySize, 65536);
    cudaFuncSetAttribute(tgemm<128,128,true,false,true,false,2,1,false>,
                         cudaFuncAttributeMaxDynamicSharedMemorySize, 65536);
    cudaFuncSetAttribute(tgemm<64,64,false,true,true,false,1,0,true>,
                         cudaFuncAttributeMaxDynamicSharedMemorySize, 32768);

    mean_kernel<<<32, 256>>>(hsi, lidar);
    dfm_kernel<<<16, 256>>>(fmg_w);
    build_kernel<<<(M2*DIMC + 255)/256, 256>>>(hsi, cls_hsi, cls_lidar, pos_hsi, pos_lidar);
    ln_frag_kernel<<<M2/8, 256>>>(X, ln1_g, ln1_b);

    prep_qv<<<DEPTH*64*1024/256, 256>>>(qkv_w);
    prep_gen<<<DEPTH*512*64/256, 256>>>(out_w, 512, 64, OFF_PROJ, DEPTH*512*64);
    prep_gen<<<DEPTH*64*256/256, 256>>>(ff_w1, 64, 256, OFF_FF1, DEPTH*64*256);
    prep_gen<<<DEPTH*256*64/256, 256>>>(ff_w2, 256, 64, OFF_FF2, DEPTH*256*64);

    for (int phase = 0; phase < 2; phase++) {
        for (int L = 0; L < DEPTH; L++) {
            const uint32_t* WL = Wf + (size_t)L*131072;
            int Ln = (L + 1) & 3;
            /* QV (A = XNf frag, Q scaled by sd in epilogue) */
            tgemm<128,128,false,false,false,true,2,1,false><<<dim3(8,226), 256, 65536>>>(
                XNf, WL + OFF_QV, nullptr, Qb, Vb, nullptr, nullptr, 64, 0, 1024, 512);
            attn_kernel<<<1024, 512, ATT_BYTES>>>();
            /* proj + residual + fused LN2 -> XNf */
            tgemm<64,64,false,true,true,false,1,0,true><<<dim3(1,452), 256, 32768>>>(
                Qb, WL + OFF_PROJ, out_b + L*64, X, nullptr,
                ln2_g + L*64, ln2_b + L*64, 512, 512, 64, 64);
            /* ff1 (A = XNf frag) + GELU */
            tgemm<128,128,true,false,true,false,2,1,false><<<dim3(2,226), 256, 65536>>>(
                XNf, WL + OFF_FF1, ff_b1 + L*256, Hb, nullptr, nullptr, nullptr, 64, 0, 256, 256);
            /* ff2 + residual + fused LN1(next layer) -> XNf */
            tgemm<64,64,false,true,true,false,1,0,true><<<dim3(1,452), 256, 32768>>>(
                Hb, WL + OFF_FF2, ff_b2 + L*64, X, nullptr,
                ln1_g + Ln*64, ln1_b + Ln*64, 256, 256, 64, 64);
        }
        if (phase == 0) swap_cls_kernel<<<16, 256>>>();
    }
    final_kernel<<<16, 256>>>((float*)d_out);
}